// round 7
// baseline (speedup 1.0000x reference)
#include <cuda_runtime.h>
#include <cstdint>

#define N_NODES 50000
#define N_EDGES 800000
#define D 128

// ---- scratch (device globals; no allocations allowed) ----
__device__ float g_agg[(size_t)N_NODES * D];
__device__ float g_h1[(size_t)N_NODES * D];
__device__ float g_h2[(size_t)N_NODES * D];
__device__ int   g_degi[N_NODES];
__device__ int   g_cursor[N_NODES];
__device__ int   g_start[N_NODES + 1];
__device__ int   g_csr_src[N_EDGES];

// zero the histogram/cursor arrays (memset nodes can't target __device__ symbols)
__global__ void zero_kernel() {
    int i = blockIdx.x * blockDim.x + threadIdx.x;
    if (i < N_NODES) { g_degi[i] = 0; g_cursor[i] = 0; }
}

// ---- CSR build: histogram of dst (edge_index is int32 on device) ----
__global__ void count_kernel(const int* __restrict__ dst) {
    int e = blockIdx.x * blockDim.x + threadIdx.x;
    if (e < N_EDGES) atomicAdd(&g_degi[dst[e]], 1);
}

// exclusive scan over N_NODES (single block, tiled)
__global__ void scan_kernel() {
    __shared__ int s[1024];
    __shared__ int s_off;
    int t = threadIdx.x;
    if (t == 0) s_off = 0;
    __syncthreads();
    for (int base = 0; base < N_NODES; base += 1024) {
        int i = base + t;
        int v = (i < N_NODES) ? g_degi[i] : 0;
        s[t] = v;
        __syncthreads();
        for (int ofs = 1; ofs < 1024; ofs <<= 1) {
            int tmp = (t >= ofs) ? s[t - ofs] : 0;
            __syncthreads();
            s[t] += tmp;
            __syncthreads();
        }
        int off = s_off;
        if (i < N_NODES) g_start[i] = off + s[t] - v;
        __syncthreads();
        if (t == 1023) s_off = off + s[1023];
        __syncthreads();
    }
    if (t == 0) g_start[N_NODES] = s_off;
}

__global__ void fill_kernel(const int* __restrict__ src,
                            const int* __restrict__ dst) {
    int e = blockIdx.x * blockDim.x + threadIdx.x;
    if (e < N_EDGES) {
        int d = dst[e];
        int pos = g_start[d] + atomicAdd(&g_cursor[d], 1);
        g_csr_src[pos] = src[e];
    }
}

// ---- mean-aggregation: one warp per node, gather + register accumulate ----
__global__ void aggregate_kernel(const float* __restrict__ feat,
                                 float* __restrict__ agg) {
    int w = (blockIdx.x * blockDim.x + threadIdx.x) >> 5;
    int lane = threadIdx.x & 31;
    if (w >= N_NODES) return;
    int s0 = g_start[w], s1 = g_start[w + 1];
    float4 acc = make_float4(0.f, 0.f, 0.f, 0.f);
    int i = s0;
    // unroll-4 for MLP
    for (; i + 4 <= s1; i += 4) {
        int a0 = g_csr_src[i + 0];
        int a1 = g_csr_src[i + 1];
        int a2 = g_csr_src[i + 2];
        int a3 = g_csr_src[i + 3];
        float4 v0 = *(const float4*)(feat + (size_t)a0 * D + lane * 4);
        float4 v1 = *(const float4*)(feat + (size_t)a1 * D + lane * 4);
        float4 v2 = *(const float4*)(feat + (size_t)a2 * D + lane * 4);
        float4 v3 = *(const float4*)(feat + (size_t)a3 * D + lane * 4);
        acc.x += (v0.x + v1.x) + (v2.x + v3.x);
        acc.y += (v0.y + v1.y) + (v2.y + v3.y);
        acc.z += (v0.z + v1.z) + (v2.z + v3.z);
        acc.w += (v0.w + v1.w) + (v2.w + v3.w);
    }
    for (; i < s1; i++) {
        int a = g_csr_src[i];
        float4 v = *(const float4*)(feat + (size_t)a * D + lane * 4);
        acc.x += v.x; acc.y += v.y; acc.z += v.z; acc.w += v.w;
    }
    float dinv = 1.f / fmaxf((float)(s1 - s0), 1.f);
    acc.x *= dinv; acc.y *= dinv; acc.z *= dinv; acc.w *= dinv;
    *(float4*)(agg + (size_t)w * D + lane * 4) = acc;
}

// ---- fused dual GEMM: out = relu(agg @ wl + feat @ wr + b) ----
// Treated as single GEMM with K=256 (rows = [agg | feat], weights = [wl ; wr]).
// Block tile 64 rows x 64 cols, 256 threads, 4x4 register micro-tile.
#define S_IN_LD 36   // pad to avoid bank conflicts (16B aligned)

__global__ void gemm_kernel(const float* __restrict__ agg,
                            const float* __restrict__ feat,
                            const float* __restrict__ wl,
                            const float* __restrict__ wr,
                            const float* __restrict__ bias,
                            float* __restrict__ out, int dout) {
    __shared__ float s_in[64][S_IN_LD];  // 64 rows x 32 k
    __shared__ float s_w[32][64];        // 32 k x 64 cols

    int row0 = blockIdx.x * 64;
    int col0 = blockIdx.y * 64;
    int t = threadIdx.x;
    int tx = t & 15;   // col group (4 cols each)
    int ty = t >> 4;   // row group (4 rows each)

    float acc[4][4];
#pragma unroll
    for (int r = 0; r < 4; r++)
#pragma unroll
        for (int c = 0; c < 4; c++) acc[r][c] = 0.f;

    for (int kc = 0; kc < 256; kc += 32) {
        // load s_in: 64 rows x 32 floats = 512 float4, 2 per thread
#pragma unroll
        for (int i = t; i < 512; i += 256) {
            int r = i >> 3;
            int kk = (i & 7) * 4;
            int row = row0 + r;
            int k = kc + kk;
            float4 v = make_float4(0.f, 0.f, 0.f, 0.f);
            if (row < N_NODES) {
                const float* p = (k < 128) ? (agg + (size_t)row * D + k)
                                           : (feat + (size_t)row * D + (k - 128));
                v = *(const float4*)p;
            }
            *(float4*)&s_in[r][kk] = v;
        }
        // load s_w: 32 k x 64 cols, scalar with guards (handles dout=40)
#pragma unroll
        for (int i = t; i < 2048; i += 256) {
            int k = i >> 6;
            int j = i & 63;
            int kg = kc + k;
            const float* w = (kg < 128) ? wl : wr;
            int krow = kg & 127;
            int col = col0 + j;
            s_w[k][j] = (col < dout) ? w[(size_t)krow * dout + col] : 0.f;
        }
        __syncthreads();
#pragma unroll
        for (int k = 0; k < 32; k++) {
            float a0 = s_in[ty * 4 + 0][k];
            float a1 = s_in[ty * 4 + 1][k];
            float a2 = s_in[ty * 4 + 2][k];
            float a3 = s_in[ty * 4 + 3][k];
            float4 wv = *(const float4*)&s_w[k][tx * 4];
            acc[0][0] += a0 * wv.x; acc[0][1] += a0 * wv.y; acc[0][2] += a0 * wv.z; acc[0][3] += a0 * wv.w;
            acc[1][0] += a1 * wv.x; acc[1][1] += a1 * wv.y; acc[1][2] += a1 * wv.z; acc[1][3] += a1 * wv.w;
            acc[2][0] += a2 * wv.x; acc[2][1] += a2 * wv.y; acc[2][2] += a2 * wv.z; acc[2][3] += a2 * wv.w;
            acc[3][0] += a3 * wv.x; acc[3][1] += a3 * wv.y; acc[3][2] += a3 * wv.z; acc[3][3] += a3 * wv.w;
        }
        __syncthreads();
    }

    // epilogue: bias + relu + store
#pragma unroll
    for (int r = 0; r < 4; r++) {
        int row = row0 + ty * 4 + r;
        if (row >= N_NODES) continue;
#pragma unroll
        for (int c = 0; c < 4; c++) {
            int col = col0 + tx * 4 + c;
            if (col < dout)
                out[(size_t)row * dout + col] = fmaxf(acc[r][c] + bias[col], 0.f);
        }
    }
}

extern "C" void kernel_launch(void* const* d_in, const int* in_sizes, int n_in,
                              void* d_out, int out_size) {
    const float* x = (const float*)d_in[0];
    const int* ei = (const int*)d_in[1];   // edge_index is int32 (JAX x64 disabled)
    const int* src = ei;
    const int* dst = ei + N_EDGES;
    const float* w1l = (const float*)d_in[2];
    const float* w1r = (const float*)d_in[3];
    const float* b1  = (const float*)d_in[4];
    const float* w2l = (const float*)d_in[5];
    const float* w2r = (const float*)d_in[6];
    const float* b2  = (const float*)d_in[7];
    const float* w3l = (const float*)d_in[8];
    const float* w3r = (const float*)d_in[9];
    const float* b3  = (const float*)d_in[10];
    float* out = (float*)d_out;

    void *p_agg, *p_h1, *p_h2;
    cudaGetSymbolAddress(&p_agg, g_agg);
    cudaGetSymbolAddress(&p_h1, g_h1);
    cudaGetSymbolAddress(&p_h2, g_h2);

    float* agg = (float*)p_agg;
    float* h1  = (float*)p_h1;
    float* h2  = (float*)p_h2;

    int nb = (N_NODES + 255) / 256;
    int eb = (N_EDGES + 255) / 256;

    zero_kernel<<<nb, 256>>>();
    count_kernel<<<eb, 256>>>(dst);
    scan_kernel<<<1, 1024>>>();
    fill_kernel<<<eb, 256>>>(src, dst);

    int ab = (N_NODES * 32 + 255) / 256;
    dim3 g128((N_NODES + 63) / 64, 2);
    dim3 g40((N_NODES + 63) / 64, 1);

    // layer 1
    aggregate_kernel<<<ab, 256>>>(x, agg);
    gemm_kernel<<<g128, 256>>>(agg, x, w1l, w1r, b1, h1, 128);
    // layer 2
    aggregate_kernel<<<ab, 256>>>(h1, agg);
    gemm_kernel<<<g128, 256>>>(agg, h1, w2l, w2r, b2, h2, 128);
    // layer 3
    aggregate_kernel<<<ab, 256>>>(h2, agg);
    gemm_kernel<<<g40, 256>>>(agg, h2, w3l, w3r, b3, out, 40);
}

// round 9
// speedup vs baseline: 1.2357x; 1.2357x over previous
#include <cuda_runtime.h>
#include <cuda_bf16.h>
#include <cstdint>

#define N_NODES 50000
#define N_EDGES 800000
#define D 128

// ---- scratch (device globals; no allocations allowed) ----
__device__ float g_agg[(size_t)N_NODES * D];
__device__ float g_h1[(size_t)N_NODES * D];
__device__ float g_h2[(size_t)N_NODES * D];
__device__ int   g_degi[N_NODES];
__device__ int   g_cursor[N_NODES];
__device__ int   g_start[N_NODES + 1];
__device__ int   g_csr_src[N_EDGES];

// ================= CSR build =================
__global__ void zero_kernel() {
    int i = blockIdx.x * blockDim.x + threadIdx.x;
    if (i < N_NODES) { g_degi[i] = 0; g_cursor[i] = 0; }
}
__global__ void count_kernel(const int* __restrict__ dst) {
    int e = blockIdx.x * blockDim.x + threadIdx.x;
    if (e < N_EDGES) atomicAdd(&g_degi[dst[e]], 1);
}
__global__ void scan_kernel() {
    __shared__ int s[1024];
    __shared__ int s_off;
    int t = threadIdx.x;
    if (t == 0) s_off = 0;
    __syncthreads();
    for (int base = 0; base < N_NODES; base += 1024) {
        int i = base + t;
        int v = (i < N_NODES) ? g_degi[i] : 0;
        s[t] = v;
        __syncthreads();
        for (int ofs = 1; ofs < 1024; ofs <<= 1) {
            int tmp = (t >= ofs) ? s[t - ofs] : 0;
            __syncthreads();
            s[t] += tmp;
            __syncthreads();
        }
        int off = s_off;
        if (i < N_NODES) g_start[i] = off + s[t] - v;
        __syncthreads();
        if (t == 1023) s_off = off + s[1023];
        __syncthreads();
    }
    if (t == 0) g_start[N_NODES] = s_off;
}
__global__ void fill_kernel(const int* __restrict__ src, const int* __restrict__ dst) {
    int e = blockIdx.x * blockDim.x + threadIdx.x;
    if (e < N_EDGES) {
        int d = dst[e];
        int pos = g_start[d] + atomicAdd(&g_cursor[d], 1);
        g_csr_src[pos] = src[e];
    }
}

// ================= mean-aggregation: one warp per node =================
__global__ void aggregate_kernel(const float* __restrict__ feat, float* __restrict__ agg) {
    int w = (blockIdx.x * blockDim.x + threadIdx.x) >> 5;
    int lane = threadIdx.x & 31;
    if (w >= N_NODES) return;
    int s0 = g_start[w], s1 = g_start[w + 1];
    float4 acc = make_float4(0.f, 0.f, 0.f, 0.f);
    int i = s0;
    for (; i + 4 <= s1; i += 4) {
        int a0 = g_csr_src[i + 0], a1 = g_csr_src[i + 1];
        int a2 = g_csr_src[i + 2], a3 = g_csr_src[i + 3];
        float4 v0 = *(const float4*)(feat + (size_t)a0 * D + lane * 4);
        float4 v1 = *(const float4*)(feat + (size_t)a1 * D + lane * 4);
        float4 v2 = *(const float4*)(feat + (size_t)a2 * D + lane * 4);
        float4 v3 = *(const float4*)(feat + (size_t)a3 * D + lane * 4);
        acc.x += (v0.x + v1.x) + (v2.x + v3.x);
        acc.y += (v0.y + v1.y) + (v2.y + v3.y);
        acc.z += (v0.z + v1.z) + (v2.z + v3.z);
        acc.w += (v0.w + v1.w) + (v2.w + v3.w);
    }
    for (; i < s1; i++) {
        int a = g_csr_src[i];
        float4 v = *(const float4*)(feat + (size_t)a * D + lane * 4);
        acc.x += v.x; acc.y += v.y; acc.z += v.z; acc.w += v.w;
    }
    float dinv = 1.f / fmaxf((float)(s1 - s0), 1.f);
    acc.x *= dinv; acc.y *= dinv; acc.z *= dinv; acc.w *= dinv;
    *(float4*)(agg + (size_t)w * D + lane * 4) = acc;
}

// ================= split-bf16 tensor-core dual GEMM (mma.sync HMMA) =================
// out[128 x dout] = relu([agg|feat] @ [wl;wr] + b), K=256 in 4 chunks of 64.
// fp32 -> bf16 hi+lo; 3 cross-term m16n8k16 MMAs, fp32 accumulators in registers.
// 8 warps: warp_m = wid&1 (64 rows each), warp_n = wid>>1 (BN/4 cols each).

#define MMA16816(d, a, b) \
    asm volatile("mma.sync.aligned.m16n8k16.row.col.f32.bf16.bf16.f32 " \
                 "{%0,%1,%2,%3},{%4,%5,%6,%7},{%8,%9},{%0,%1,%2,%3};" \
                 : "+f"((d)[0]), "+f"((d)[1]), "+f"((d)[2]), "+f"((d)[3]) \
                 : "r"((a)[0]), "r"((a)[1]), "r"((a)[2]), "r"((a)[3]), \
                   "r"((b)[0]), "r"((b)[1]))

template <int BN>
__global__ void __launch_bounds__(256, 1)
hmma_gemm_kernel(const float* __restrict__ agg, const float* __restrict__ feat,
                 const float* __restrict__ wl,  const float* __restrict__ wr,
                 const float* __restrict__ bias, float* __restrict__ out, int dout) {
    extern __shared__ char smem[];
    constexpr int PITCH = 72;                        // bf16 elems/row (pad: conflict-free frags)
    constexpr int A_HI = 0;
    constexpr int A_LO = 128 * PITCH * 2;
    constexpr int B_HI = 2 * 128 * PITCH * 2;
    constexpr int B_LO = B_HI + BN * PITCH * 2;
    constexpr int NFRAG = BN / 32;                   // n-frags per warp (warp n-tile = BN/4)

    int tid = threadIdx.x, wid = tid >> 5, lane = tid & 31;
    int g = lane >> 2, tig = lane & 3;
    int warp_m = wid & 1, warp_n = wid >> 1;
    int row0 = blockIdx.x * 128;

    float acc[4][NFRAG][4];
#pragma unroll
    for (int m = 0; m < 4; m++)
#pragma unroll
        for (int nf = 0; nf < NFRAG; nf++)
#pragma unroll
            for (int j = 0; j < 4; j++) acc[m][nf][j] = 0.f;

    for (int ch = 0; ch < 4; ch++) {
        const float* asrc = (ch < 2) ? agg : feat;
        const float* wsrc = (ch < 2) ? wl : wr;
        int koff = (ch & 1) * 64;

        __syncthreads();
        // ---- A tile: 128 rows x 64 k, fp32 -> bf16 hi/lo ----
        for (int i = tid; i < 2048; i += 256) {
            int r = i >> 4;
            int kq = (i & 15) << 2;
            float4 v = make_float4(0.f, 0.f, 0.f, 0.f);
            int row = row0 + r;
            if (row < N_NODES) v = *(const float4*)(asrc + (size_t)row * D + koff + kq);
            __nv_bfloat16 h0 = __float2bfloat16(v.x), h1 = __float2bfloat16(v.y);
            __nv_bfloat16 h2 = __float2bfloat16(v.z), h3 = __float2bfloat16(v.w);
            __nv_bfloat16 l0 = __float2bfloat16(v.x - __bfloat162float(h0));
            __nv_bfloat16 l1 = __float2bfloat16(v.y - __bfloat162float(h1));
            __nv_bfloat16 l2 = __float2bfloat16(v.z - __bfloat162float(h2));
            __nv_bfloat16 l3 = __float2bfloat16(v.w - __bfloat162float(h3));
            uint2 hp, lp;
            hp.x = (uint32_t)__bfloat16_as_ushort(h0) | ((uint32_t)__bfloat16_as_ushort(h1) << 16);
            hp.y = (uint32_t)__bfloat16_as_ushort(h2) | ((uint32_t)__bfloat16_as_ushort(h3) << 16);
            lp.x = (uint32_t)__bfloat16_as_ushort(l0) | ((uint32_t)__bfloat16_as_ushort(l1) << 16);
            lp.y = (uint32_t)__bfloat16_as_ushort(l2) | ((uint32_t)__bfloat16_as_ushort(l3) << 16);
            int off = (r * PITCH + kq) * 2;
            *(uint2*)(smem + A_HI + off) = hp;
            *(uint2*)(smem + A_LO + off) = lp;
        }
        // ---- B tile: BN n-rows x 64 k, from w[k][n] (transpose), hi/lo ----
        constexpr int G4 = BN / 4;
        for (int i = tid; i < 16 * BN; i += 256) {
            int k = i / G4;
            int n4 = (i - k * G4) * 4;
            float4 v = make_float4(0.f, 0.f, 0.f, 0.f);
            if (n4 + 4 <= dout) v = *(const float4*)(wsrc + (size_t)(koff + k) * dout + n4);
            float fx[4] = {v.x, v.y, v.z, v.w};
#pragma unroll
            for (int j = 0; j < 4; j++) {
                __nv_bfloat16 h = __float2bfloat16(fx[j]);
                __nv_bfloat16 l = __float2bfloat16(fx[j] - __bfloat162float(h));
                int off = ((n4 + j) * PITCH + k) * 2;
                *(__nv_bfloat16*)(smem + B_HI + off) = h;
                *(__nv_bfloat16*)(smem + B_LO + off) = l;
            }
        }
        __syncthreads();

        // ---- MMA: 4 k16 steps x (hi*hi + hi*lo + lo*hi) ----
#pragma unroll
        for (int ks = 0; ks < 4; ks++) {
            int kb = ks * 16 + 2 * tig;
            uint32_t ahi[4][4], alo[4][4];
#pragma unroll
            for (int m = 0; m < 4; m++) {
                int r = warp_m * 64 + m * 16 + g;
                int o = (r * PITCH + kb) * 2;
                ahi[m][0] = *(const uint32_t*)(smem + A_HI + o);
                ahi[m][1] = *(const uint32_t*)(smem + A_HI + o + 8 * PITCH * 2);
                ahi[m][2] = *(const uint32_t*)(smem + A_HI + o + 16);
                ahi[m][3] = *(const uint32_t*)(smem + A_HI + o + 8 * PITCH * 2 + 16);
                alo[m][0] = *(const uint32_t*)(smem + A_LO + o);
                alo[m][1] = *(const uint32_t*)(smem + A_LO + o + 8 * PITCH * 2);
                alo[m][2] = *(const uint32_t*)(smem + A_LO + o + 16);
                alo[m][3] = *(const uint32_t*)(smem + A_LO + o + 8 * PITCH * 2 + 16);
            }
            uint32_t bhi[NFRAG][2], blo[NFRAG][2];
#pragma unroll
            for (int nf = 0; nf < NFRAG; nf++) {
                int n = warp_n * (BN / 4) + nf * 8 + g;
                int o = (n * PITCH + kb) * 2;
                bhi[nf][0] = *(const uint32_t*)(smem + B_HI + o);
                bhi[nf][1] = *(const uint32_t*)(smem + B_HI + o + 16);
                blo[nf][0] = *(const uint32_t*)(smem + B_LO + o);
                blo[nf][1] = *(const uint32_t*)(smem + B_LO + o + 16);
            }
#pragma unroll
            for (int m = 0; m < 4; m++)
#pragma unroll
                for (int nf = 0; nf < NFRAG; nf++) {
                    MMA16816(acc[m][nf], ahi[m], bhi[nf]);
                    MMA16816(acc[m][nf], ahi[m], blo[nf]);
                    MMA16816(acc[m][nf], alo[m], bhi[nf]);
                }
        }
    }

    // ---- epilogue: bias + relu + store ----
#pragma unroll
    for (int m = 0; m < 4; m++) {
        int row = row0 + warp_m * 64 + m * 16 + g;
#pragma unroll
        for (int nf = 0; nf < NFRAG; nf++) {
            int col = warp_n * (BN / 4) + nf * 8 + 2 * tig;
            if (col < dout) {
                float bc0 = bias[col], bc1 = bias[col + 1];
                if (row < N_NODES) {
                    out[(size_t)row * dout + col]     = fmaxf(acc[m][nf][0] + bc0, 0.f);
                    out[(size_t)row * dout + col + 1] = fmaxf(acc[m][nf][1] + bc1, 0.f);
                }
                if (row + 8 < N_NODES) {
                    out[(size_t)(row + 8) * dout + col]     = fmaxf(acc[m][nf][2] + bc0, 0.f);
                    out[(size_t)(row + 8) * dout + col + 1] = fmaxf(acc[m][nf][3] + bc1, 0.f);
                }
            }
        }
    }
}

// ================= launch =================
extern "C" void kernel_launch(void* const* d_in, const int* in_sizes, int n_in,
                              void* d_out, int out_size) {
    const float* x = (const float*)d_in[0];
    const int* ei = (const int*)d_in[1];   // edge_index is int32 on device
    const int* src = ei;
    const int* dst = ei + N_EDGES;
    const float* w1l = (const float*)d_in[2];
    const float* w1r = (const float*)d_in[3];
    const float* b1  = (const float*)d_in[4];
    const float* w2l = (const float*)d_in[5];
    const float* w2r = (const float*)d_in[6];
    const float* b2  = (const float*)d_in[7];
    const float* w3l = (const float*)d_in[8];
    const float* w3r = (const float*)d_in[9];
    const float* b3  = (const float*)d_in[10];
    float* out = (float*)d_out;

    void *p_agg, *p_h1, *p_h2;
    cudaGetSymbolAddress(&p_agg, g_agg);
    cudaGetSymbolAddress(&p_h1, g_h1);
    cudaGetSymbolAddress(&p_h2, g_h2);
    float* agg = (float*)p_agg;
    float* h1  = (float*)p_h1;
    float* h2  = (float*)p_h2;

    const int SMEM128 = 2 * 128 * 72 * 2 + 2 * 128 * 72 * 2;  // 73728
    const int SMEM64  = 2 * 128 * 72 * 2 + 2 * 64 * 72 * 2;   // 55296
    cudaFuncSetAttribute(hmma_gemm_kernel<128>, cudaFuncAttributeMaxDynamicSharedMemorySize, SMEM128);
    cudaFuncSetAttribute(hmma_gemm_kernel<64>,  cudaFuncAttributeMaxDynamicSharedMemorySize, SMEM64);

    int nb = (N_NODES + 255) / 256;
    int eb = (N_EDGES + 255) / 256;
    int gb = (N_NODES + 127) / 128;

    zero_kernel<<<nb, 256>>>();
    count_kernel<<<eb, 256>>>(dst);
    scan_kernel<<<1, 1024>>>();
    fill_kernel<<<eb, 256>>>(src, dst);

    int ab = (N_NODES * 32 + 255) / 256;

    // layer 1
    aggregate_kernel<<<ab, 256>>>(x, agg);
    hmma_gemm_kernel<128><<<gb, 256, SMEM128>>>(agg, x, w1l, w1r, b1, h1, 128);
    // layer 2
    aggregate_kernel<<<ab, 256>>>(h1, agg);
    hmma_gemm_kernel<128><<<gb, 256, SMEM128>>>(agg, h1, w2l, w2r, b2, h2, 128);
    // layer 3
    aggregate_kernel<<<ab, 256>>>(h2, agg);
    hmma_gemm_kernel<64><<<gb, 256, SMEM64>>>(agg, h2, w3l, w3r, b3, out, 40);
}

// round 10
// speedup vs baseline: 1.2932x; 1.0465x over previous
#include <cuda_runtime.h>
#include <cuda_bf16.h>
#include <cstdint>

#define N_NODES 50000
#define N_EDGES 800000
#define D 128

// ---- scratch (device globals; no allocations allowed) ----
__device__ float g_agg[(size_t)N_NODES * D];
__device__ float g_h1[(size_t)N_NODES * D];
__device__ float g_h2[(size_t)N_NODES * D];
__device__ int   g_degi[N_NODES];
__device__ int   g_cursor[N_NODES];
__device__ int   g_start[N_NODES + 1];
__device__ int   g_csr_src[N_EDGES];

// ================= CSR build =================
__global__ void zero_kernel() {
    int i = blockIdx.x * blockDim.x + threadIdx.x;
    if (i < N_NODES) { g_degi[i] = 0; g_cursor[i] = 0; }
}
__global__ void count_kernel(const int* __restrict__ dst) {
    int e = blockIdx.x * blockDim.x + threadIdx.x;
    if (e < N_EDGES) atomicAdd(&g_degi[dst[e]], 1);
}

// exclusive scan: serial-per-thread + shuffle block scan (1 block, 1024 thr)
__global__ void scan_kernel() {
    constexpr int PER = (N_NODES + 1023) / 1024;  // 49
    __shared__ int wsum[32];
    int t = threadIdx.x;
    int lane = t & 31, wid = t >> 5;
    int base = t * PER;

    int s = 0;
#pragma unroll 7
    for (int j = 0; j < PER; j++) {
        int i = base + j;
        if (i < N_NODES) s += g_degi[i];
    }
    // warp inclusive scan of thread totals
    int v = s;
#pragma unroll
    for (int o = 1; o < 32; o <<= 1) {
        int u = __shfl_up_sync(0xFFFFFFFFu, v, o);
        if (lane >= o) v += u;
    }
    if (lane == 31) wsum[wid] = v;
    __syncthreads();
    if (wid == 0) {
        int w = wsum[lane];
#pragma unroll
        for (int o = 1; o < 32; o <<= 1) {
            int u = __shfl_up_sync(0xFFFFFFFFu, w, o);
            if (lane >= o) w += u;
        }
        wsum[lane] = w;
    }
    __syncthreads();
    int run = (v - s) + (wid > 0 ? wsum[wid - 1] : 0);  // exclusive prefix for this thread
#pragma unroll 7
    for (int j = 0; j < PER; j++) {
        int i = base + j;
        if (i < N_NODES) {
            int d = g_degi[i];
            g_start[i] = run;
            run += d;
        }
    }
    if (t == 1023) g_start[N_NODES] = run;
}

__global__ void fill_kernel(const int* __restrict__ src, const int* __restrict__ dst) {
    int e = blockIdx.x * blockDim.x + threadIdx.x;
    if (e < N_EDGES) {
        int d = dst[e];
        int pos = g_start[d] + atomicAdd(&g_cursor[d], 1);
        g_csr_src[pos] = src[e];
    }
}

// ================= mean-aggregation: one warp per node =================
__global__ void aggregate_kernel(const float* __restrict__ feat, float* __restrict__ agg) {
    int w = (blockIdx.x * blockDim.x + threadIdx.x) >> 5;
    int lane = threadIdx.x & 31;
    if (w >= N_NODES) return;
    int s0 = g_start[w], s1 = g_start[w + 1];
    float4 acc = make_float4(0.f, 0.f, 0.f, 0.f);
    int i = s0;
    for (; i + 4 <= s1; i += 4) {
        int a0 = g_csr_src[i + 0], a1 = g_csr_src[i + 1];
        int a2 = g_csr_src[i + 2], a3 = g_csr_src[i + 3];
        float4 v0 = *(const float4*)(feat + (size_t)a0 * D + lane * 4);
        float4 v1 = *(const float4*)(feat + (size_t)a1 * D + lane * 4);
        float4 v2 = *(const float4*)(feat + (size_t)a2 * D + lane * 4);
        float4 v3 = *(const float4*)(feat + (size_t)a3 * D + lane * 4);
        acc.x += (v0.x + v1.x) + (v2.x + v3.x);
        acc.y += (v0.y + v1.y) + (v2.y + v3.y);
        acc.z += (v0.z + v1.z) + (v2.z + v3.z);
        acc.w += (v0.w + v1.w) + (v2.w + v3.w);
    }
    for (; i < s1; i++) {
        int a = g_csr_src[i];
        float4 v = *(const float4*)(feat + (size_t)a * D + lane * 4);
        acc.x += v.x; acc.y += v.y; acc.z += v.z; acc.w += v.w;
    }
    float dinv = 1.f / fmaxf((float)(s1 - s0), 1.f);
    acc.x *= dinv; acc.y *= dinv; acc.z *= dinv; acc.w *= dinv;
    *(float4*)(agg + (size_t)w * D + lane * 4) = acc;
}

// ================= split-bf16 tensor-core dual GEMM (mma.sync + ldmatrix) =================
#define MMA16816(d, a, b) \
    asm volatile("mma.sync.aligned.m16n8k16.row.col.f32.bf16.bf16.f32 " \
                 "{%0,%1,%2,%3},{%4,%5,%6,%7},{%8,%9},{%0,%1,%2,%3};" \
                 : "+f"((d)[0]), "+f"((d)[1]), "+f"((d)[2]), "+f"((d)[3]) \
                 : "r"((a)[0]), "r"((a)[1]), "r"((a)[2]), "r"((a)[3]), \
                   "r"((b)[0]), "r"((b)[1]))

#define LDMX4(r, a) \
    asm volatile("ldmatrix.sync.aligned.m8n8.x4.shared.b16 {%0,%1,%2,%3}, [%4];" \
                 : "=r"((r)[0]), "=r"((r)[1]), "=r"((r)[2]), "=r"((r)[3]) : "r"(a))

__device__ __forceinline__ uint32_t smem_u32(const void* p) {
    uint32_t a;
    asm("{ .reg .u64 t; cvta.to.shared.u64 t, %1; cvt.u32.u64 %0, t; }" : "=r"(a) : "l"(p));
    return a;
}

template <int BN>
__global__ void __launch_bounds__(256, 1)
hmma_gemm_kernel(const float* __restrict__ agg, const float* __restrict__ feat,
                 const float* __restrict__ wl,  const float* __restrict__ wr,
                 const float* __restrict__ bias, float* __restrict__ out, int dout) {
    extern __shared__ char smem[];
    constexpr int PITCH = 72;                        // bf16 elems/row
    constexpr int A_HI = 0;
    constexpr int A_LO = 128 * PITCH * 2;
    constexpr int B_HI = 2 * 128 * PITCH * 2;
    constexpr int B_LO = B_HI + BN * PITCH * 2;
    constexpr int NFRAG = BN / 32;                   // n-frags per warp
    constexpr int G4 = BN / 4;                       // float4 cols of B
    constexpr int BITER = BN / 16;                   // B fill iters per thread

    int tid = threadIdx.x, wid = tid >> 5, lane = tid & 31;
    int g = lane >> 2, tig = lane & 3;
    int warp_m = wid & 1, warp_n = wid >> 1;
    int row0 = blockIdx.x * 128;
    uint32_t sb = smem_u32(smem);

    float acc[4][NFRAG][4];
#pragma unroll
    for (int m = 0; m < 4; m++)
#pragma unroll
        for (int nf = 0; nf < NFRAG; nf++)
#pragma unroll
            for (int j = 0; j < 4; j++) acc[m][nf][j] = 0.f;

    // ldmatrix lane addresses (byte offsets within tile, recomputed per ks via +)
    int a_row = warp_m * 64 + (lane & 15);
    int a_kof = (lane >> 4) << 3;
    int b_n0  = warp_n * (BN / 4) + ((lane >> 3) & 1) * 8 + (lane & 7);
    int b_kof = (lane >> 4) << 3;

    float4 pa[8];   // A-chunk prefetch registers

    // prefetch chunk 0
    {
        const float* asrc = agg;
#pragma unroll
        for (int j = 0; j < 8; j++) {
            int i = tid + j * 256;
            int r = i >> 4, kq = (i & 15) << 2;
            int row = row0 + r;
            pa[j] = (row < N_NODES) ? *(const float4*)(asrc + (size_t)row * D + kq)
                                    : make_float4(0.f, 0.f, 0.f, 0.f);
        }
    }

    for (int ch = 0; ch < 4; ch++) {
        const float* wsrc = (ch < 2) ? wl : wr;
        int koff = (ch & 1) * 64;

        __syncthreads();   // previous MMA phase done; smem free

        // ---- convert prefetched A regs -> smem hi/lo ----
#pragma unroll
        for (int j = 0; j < 8; j++) {
            int i = tid + j * 256;
            int r = i >> 4, kq = (i & 15) << 2;
            float4 v = pa[j];
            __nv_bfloat16 h0 = __float2bfloat16(v.x), h1 = __float2bfloat16(v.y);
            __nv_bfloat16 h2 = __float2bfloat16(v.z), h3 = __float2bfloat16(v.w);
            __nv_bfloat16 l0 = __float2bfloat16(v.x - __bfloat162float(h0));
            __nv_bfloat16 l1 = __float2bfloat16(v.y - __bfloat162float(h1));
            __nv_bfloat16 l2 = __float2bfloat16(v.z - __bfloat162float(h2));
            __nv_bfloat16 l3 = __float2bfloat16(v.w - __bfloat162float(h3));
            uint2 hp, lp;
            hp.x = (uint32_t)__bfloat16_as_ushort(h0) | ((uint32_t)__bfloat16_as_ushort(h1) << 16);
            hp.y = (uint32_t)__bfloat16_as_ushort(h2) | ((uint32_t)__bfloat16_as_ushort(h3) << 16);
            lp.x = (uint32_t)__bfloat16_as_ushort(l0) | ((uint32_t)__bfloat16_as_ushort(l1) << 16);
            lp.y = (uint32_t)__bfloat16_as_ushort(l2) | ((uint32_t)__bfloat16_as_ushort(l3) << 16);
            int off = (r * PITCH + kq) * 2;
            *(uint2*)(smem + A_HI + off) = hp;
            *(uint2*)(smem + A_LO + off) = lp;
        }
        // ---- B tile: BN n-rows x 64 k (transpose from w[k][n], hi/lo) ----
#pragma unroll
        for (int j = 0; j < BITER; j++) {
            int i = tid + j * 256;
            int k = i / G4;
            int n4 = (i - k * G4) * 4;
            float4 v = make_float4(0.f, 0.f, 0.f, 0.f);
            if (n4 + 4 <= dout) v = *(const float4*)(wsrc + (size_t)(koff + k) * dout + n4);
            float fx[4] = {v.x, v.y, v.z, v.w};
#pragma unroll
            for (int jj = 0; jj < 4; jj++) {
                __nv_bfloat16 h = __float2bfloat16(fx[jj]);
                __nv_bfloat16 l = __float2bfloat16(fx[jj] - __bfloat162float(h));
                int off = ((n4 + jj) * PITCH + k) * 2;
                *(__nv_bfloat16*)(smem + B_HI + off) = h;
                *(__nv_bfloat16*)(smem + B_LO + off) = l;
            }
        }
        __syncthreads();

        // ---- prefetch next A chunk (LDG latency hides under MMA) ----
        if (ch < 3) {
            const float* asrc2 = (ch + 1 < 2) ? agg : feat;
            int koff2 = ((ch + 1) & 1) * 64;
#pragma unroll
            for (int j = 0; j < 8; j++) {
                int i = tid + j * 256;
                int r = i >> 4, kq = (i & 15) << 2;
                int row = row0 + r;
                pa[j] = (row < N_NODES) ? *(const float4*)(asrc2 + (size_t)row * D + koff2 + kq)
                                        : make_float4(0.f, 0.f, 0.f, 0.f);
            }
        }

        // ---- MMA: 4 k16 steps x (hi*hi + hi*lo + lo*hi), ldmatrix frags ----
#pragma unroll
        for (int ks = 0; ks < 4; ks++) {
            int kb = ks * 16;
            uint32_t ahi[4][4], alo[4][4];
#pragma unroll
            for (int m = 0; m < 4; m++) {
                uint32_t ao = sb + (uint32_t)(((a_row + m * 16) * PITCH + kb + a_kof) * 2);
                LDMX4(ahi[m], ao + A_HI);
                LDMX4(alo[m], ao + A_LO);
            }
            uint32_t bhi[NFRAG][2], blo[NFRAG][2];
#pragma unroll
            for (int p = 0; p < NFRAG / 2; p++) {
                uint32_t bo = sb + (uint32_t)(((b_n0 + p * 16) * PITCH + kb + b_kof) * 2);
                uint32_t rh[4], rl[4];
                LDMX4(rh, bo + B_HI);
                LDMX4(rl, bo + B_LO);
                bhi[2 * p][0] = rh[0]; bhi[2 * p + 1][0] = rh[1];
                bhi[2 * p][1] = rh[2]; bhi[2 * p + 1][1] = rh[3];
                blo[2 * p][0] = rl[0]; blo[2 * p + 1][0] = rl[1];
                blo[2 * p][1] = rl[2]; blo[2 * p + 1][1] = rl[3];
            }
#pragma unroll
            for (int m = 0; m < 4; m++)
#pragma unroll
                for (int nf = 0; nf < NFRAG; nf++) {
                    MMA16816(acc[m][nf], ahi[m], bhi[nf]);
                    MMA16816(acc[m][nf], ahi[m], blo[nf]);
                    MMA16816(acc[m][nf], alo[m], bhi[nf]);
                }
        }
    }

    // ---- epilogue: bias + relu + store ----
#pragma unroll
    for (int m = 0; m < 4; m++) {
        int row = row0 + warp_m * 64 + m * 16 + g;
#pragma unroll
        for (int nf = 0; nf < NFRAG; nf++) {
            int col = warp_n * (BN / 4) + nf * 8 + 2 * tig;
            if (col < dout) {
                float bc0 = bias[col], bc1 = bias[col + 1];
                if (row < N_NODES) {
                    out[(size_t)row * dout + col]     = fmaxf(acc[m][nf][0] + bc0, 0.f);
                    out[(size_t)row * dout + col + 1] = fmaxf(acc[m][nf][1] + bc1, 0.f);
                }
                if (row + 8 < N_NODES) {
                    out[(size_t)(row + 8) * dout + col]     = fmaxf(acc[m][nf][2] + bc0, 0.f);
                    out[(size_t)(row + 8) * dout + col + 1] = fmaxf(acc[m][nf][3] + bc1, 0.f);
                }
            }
        }
    }
}

// ================= launch =================
extern "C" void kernel_launch(void* const* d_in, const int* in_sizes, int n_in,
                              void* d_out, int out_size) {
    const float* x = (const float*)d_in[0];
    const int* ei = (const int*)d_in[1];   // edge_index is int32 on device
    const int* src = ei;
    const int* dst = ei + N_EDGES;
    const float* w1l = (const float*)d_in[2];
    const float* w1r = (const float*)d_in[3];
    const float* b1  = (const float*)d_in[4];
    const float* w2l = (const float*)d_in[5];
    const float* w2r = (const float*)d_in[6];
    const float* b2  = (const float*)d_in[7];
    const float* w3l = (const float*)d_in[8];
    const float* w3r = (const float*)d_in[9];
    const float* b3  = (const float*)d_in[10];
    float* out = (float*)d_out;

    void *p_agg, *p_h1, *p_h2;
    cudaGetSymbolAddress(&p_agg, g_agg);
    cudaGetSymbolAddress(&p_h1, g_h1);
    cudaGetSymbolAddress(&p_h2, g_h2);
    float* agg = (float*)p_agg;
    float* h1  = (float*)p_h1;
    float* h2  = (float*)p_h2;

    const int SMEM128 = 2 * 128 * 72 * 2 + 2 * 128 * 72 * 2;  // 73728
    const int SMEM64  = 2 * 128 * 72 * 2 + 2 * 64 * 72 * 2;   // 55296
    cudaFuncSetAttribute(hmma_gemm_kernel<128>, cudaFuncAttributeMaxDynamicSharedMemorySize, SMEM128);
    cudaFuncSetAttribute(hmma_gemm_kernel<64>,  cudaFuncAttributeMaxDynamicSharedMemorySize, SMEM64);

    int nb = (N_NODES + 255) / 256;
    int eb = (N_EDGES + 255) / 256;
    int gb = (N_NODES + 127) / 128;

    zero_kernel<<<nb, 256>>>();
    count_kernel<<<eb, 256>>>(dst);
    scan_kernel<<<1, 1024>>>();
    fill_kernel<<<eb, 256>>>(src, dst);

    int ab = (N_NODES * 32 + 255) / 256;

    // layer 1
    aggregate_kernel<<<ab, 256>>>(x, agg);
    hmma_gemm_kernel<128><<<gb, 256, SMEM128>>>(agg, x, w1l, w1r, b1, h1, 128);
    // layer 2
    aggregate_kernel<<<ab, 256>>>(h1, agg);
    hmma_gemm_kernel<128><<<gb, 256, SMEM128>>>(agg, h1, w2l, w2r, b2, h2, 128);
    // layer 3
    aggregate_kernel<<<ab, 256>>>(h2, agg);
    hmma_gemm_kernel<64><<<gb, 256, SMEM64>>>(agg, h2, w3l, w3r, b3, out, 40);
}